// round 7
// baseline (speedup 1.0000x reference)
#include <cuda_runtime.h>
#include <cuda_bf16.h>
#include <math.h>
#include <stdint.h>

#define Bb 8
#define Ss 256
#define Tt 32
#define Dd 512
#define NROWS 2048   // B*S
#define MROWS 256    // B*T

// Scratch (allocation-free rule: __device__ globals)
__device__ float g_H[NROWS * Dd];
__device__ float g_F[NROWS * Dd];
__device__ float g_A[MROWS * Dd];
__device__ float g_C[MROWS * Dd];

// Pre-split bf16 hi/lo planes for every GEMM operand (hi plane then lo plane)
#define ENC_OFF 0
#define ENC_SZ  1048576
#define Z_OFF   2097152
#define Z_SZ    262144
#define OUT_OFF 2621440
#define OUT_SZ  131072
#define W1_OFF  2883584
#define W2_OFF  3407872
#define W3_OFF  3932160
#define W4_OFF  4063232
#define W_SZ    262144
#define W3_SZ   65536
__device__ __nv_bfloat16 g_bf[4587520];

// ---------------------------------------------------------------------------
// helpers
// ---------------------------------------------------------------------------
__device__ __forceinline__ uint32_t smem_to_u32(const void* p) {
    uint32_t a;
    asm("{ .reg .u64 t; cvta.to.shared.u64 t, %1; cvt.u32.u64 %0, t; }"
        : "=r"(a) : "l"(p));
    return a;
}
__device__ __forceinline__ void ldsm_x4(uint32_t* r, uint32_t addr) {
    asm volatile("ldmatrix.sync.aligned.m8n8.x4.shared.b16 {%0,%1,%2,%3}, [%4];"
        : "=r"(r[0]), "=r"(r[1]), "=r"(r[2]), "=r"(r[3]) : "r"(addr));
}
__device__ __forceinline__ void ldsm_x4_t(uint32_t* r, uint32_t addr) {
    asm volatile("ldmatrix.sync.aligned.m8n8.x4.trans.shared.b16 {%0,%1,%2,%3}, [%4];"
        : "=r"(r[0]), "=r"(r[1]), "=r"(r[2]), "=r"(r[3]) : "r"(addr));
}
__device__ __forceinline__ void mma_bf16(float* d, const uint32_t* a, const uint32_t* b) {
    asm volatile("mma.sync.aligned.m16n8k16.row.col.f32.bf16.bf16.f32 "
        "{%0,%1,%2,%3}, {%4,%5,%6,%7}, {%8,%9}, {%0,%1,%2,%3};"
        : "+f"(d[0]), "+f"(d[1]), "+f"(d[2]), "+f"(d[3])
        : "r"(a[0]), "r"(a[1]), "r"(a[2]), "r"(a[3]), "r"(b[0]), "r"(b[1]));
}
__device__ __forceinline__ uint32_t pb2(__nv_bfloat16 a, __nv_bfloat16 b) {
    __nv_bfloat162 t; t.x = a; t.y = b;
    return *(uint32_t*)&t;
}
__device__ __forceinline__ void cpa16(uint32_t s, const void* g) {
    asm volatile("cp.async.cg.shared.global [%0], [%1], 16;" :: "r"(s), "l"(g));
}
#define CP_COMMIT() asm volatile("cp.async.commit_group;" ::: "memory")

// ---------------------------------------------------------------------------
// Kernel 0: split every fp32 operand into bf16 hi + lo planes (once).
// 573440 float4 items, grid 560 x 1024.
// ---------------------------------------------------------------------------
__global__ void __launch_bounds__(1024)
convert_all(const float* __restrict__ enc, const float* __restrict__ z,
            const float* __restrict__ outp,
            const float* __restrict__ W1, const float* __restrict__ W2,
            const float* __restrict__ W3, const float* __restrict__ W4)
{
    int e = (blockIdx.x * 1024 + threadIdx.x) * 4;
    const float* src; int base, size, local;
    if (e < 1048576)      { src = enc;  base = ENC_OFF; size = ENC_SZ; local = e; }
    else if (e < 1310720) { src = z;    base = Z_OFF;   size = Z_SZ;   local = e - 1048576; }
    else if (e < 1441792) { src = outp; base = OUT_OFF; size = OUT_SZ; local = e - 1310720; }
    else if (e < 1703936) { src = W1;   base = W1_OFF;  size = W_SZ;   local = e - 1441792; }
    else if (e < 1966080) { src = W2;   base = W2_OFF;  size = W_SZ;   local = e - 1703936; }
    else if (e < 2031616) { src = W3;   base = W3_OFF;  size = W3_SZ;  local = e - 1966080; }
    else                  { src = W4;   base = W4_OFF;  size = W_SZ;   local = e - 2031616; }
    float4 v = *(const float4*)(src + local);
    float xs[4] = {v.x, v.y, v.z, v.w};
    __nv_bfloat16 h[4], l[4];
    #pragma unroll
    for (int j = 0; j < 4; j++) {
        h[j] = __float2bfloat16_rn(xs[j]);
        l[j] = __float2bfloat16_rn(xs[j] - __bfloat162float(h[j]));
    }
    uint2 uh; uh.x = pb2(h[0], h[1]); uh.y = pb2(h[2], h[3]);
    uint2 ul; ul.x = pb2(l[0], l[1]); ul.y = pb2(l[2], l[3]);
    *(uint2*)&g_bf[base + local] = uh;
    *(uint2*)&g_bf[base + size + local] = ul;
}

// ---------------------------------------------------------------------------
// Mega-GEMM: out = tanh(src @ W + bias), bf16 hi/lo split (3 MMAs/term),
// cp.async 2-stage pipeline, CTA 128m x 64n, BK=32, 8 warps (4m x 2n).
// smem per stage (bytes): Ahi[128*40*2]=10240 | Alo 10240 | Bhi[32*72*2]=4608
// | Blo 4608 -> 29696; two stages = 59392 -> 2 CTAs/SM.
// Blocks: [0,128) H | [128,144) A | [144,160) C | [160,288) F (light tail)
// ---------------------------------------------------------------------------
#define STG_B 29696
#define GEMM_SMEM (2 * STG_B)

__global__ void __launch_bounds__(256, 2)
megagemm_mma(const float* __restrict__ b1, const float* __restrict__ b2,
             const float* __restrict__ b3, const float* __restrict__ b4,
             float* __restrict__ H, float* __restrict__ F,
             float* __restrict__ A, float* __restrict__ C)
{
    extern __shared__ char sbuf[];
    const uint32_t sb0 = smem_to_u32(sbuf);

    int bid = blockIdx.x;
    int a_off, a_sz, b_off, b_sz, K;
    const float* bias; float* dst;
    if (bid < 128)      { a_off=ENC_OFF; a_sz=ENC_SZ; b_off=W1_OFF; b_sz=W_SZ;  bias=b1; dst=H; K=512; }
    else if (bid < 144) { a_off=OUT_OFF; a_sz=OUT_SZ; b_off=W2_OFF; b_sz=W_SZ;  bias=b2; dst=A; K=512; bid-=128; }
    else if (bid < 160) { a_off=OUT_OFF; a_sz=OUT_SZ; b_off=W4_OFF; b_sz=W_SZ;  bias=b4; dst=C; K=512; bid-=144; }
    else                { a_off=Z_OFF;   a_sz=Z_SZ;   b_off=W3_OFF; b_sz=W3_SZ; bias=b3; dst=F; K=128; bid-=160; }
    const int nb = bid & 7;
    const int mb = bid >> 3;
    const int m0 = mb * 128, n0 = nb * 64;

    const __nv_bfloat16* Ah_g = g_bf + a_off;
    const __nv_bfloat16* Al_g = g_bf + a_off + a_sz;
    const __nv_bfloat16* Bh_g = g_bf + b_off;
    const __nv_bfloat16* Bl_g = g_bf + b_off + b_sz;

    const int tid  = threadIdx.x;
    const int lane = tid & 31;
    const int wid  = tid >> 5;
    const int wm   = wid & 3;     // 32 m rows
    const int wn   = wid >> 2;    // 32 n cols

    // staging coordinates
    const int arow = tid >> 1, ak = (tid & 1) * 16;
    const int brow = tid >> 3, bc = (tid & 7) * 8;

    float acc[2][4][4];
    #pragma unroll
    for (int i = 0; i < 2; i++)
        #pragma unroll
        for (int j = 0; j < 4; j++)
            #pragma unroll
            for (int q = 0; q < 4; q++) acc[i][j][q] = 0.f;

    const int nch = K >> 5;

    auto issue = [&](int c, int buf) {
        const int k0 = c * 32;
        const uint32_t sb = sb0 + buf * STG_B;
        size_t as = (size_t)(m0 + arow) * K + k0 + ak;
        uint32_t ad = sb + arow * 80 + ak * 2;
        cpa16(ad,              Ah_g + as);
        cpa16(ad + 16,         Ah_g + as + 8);
        cpa16(ad + 10240,      Al_g + as);
        cpa16(ad + 10240 + 16, Al_g + as + 8);
        size_t bs = (size_t)(k0 + brow) * 512 + n0 + bc;
        uint32_t bd = sb + 20480 + brow * 144 + bc * 2;
        cpa16(bd,        Bh_g + bs);
        cpa16(bd + 4608, Bl_g + bs);
    };

    issue(0, 0); CP_COMMIT();

    for (int c = 0; c < nch; c++) {
        const int buf = c & 1;
        if (c + 1 < nch) {
            issue(c + 1, buf ^ 1); CP_COMMIT();
            asm volatile("cp.async.wait_group 1;" ::: "memory");
        } else {
            asm volatile("cp.async.wait_group 0;" ::: "memory");
        }
        __syncthreads();

        const uint32_t aHiB = sb0 + buf * STG_B;
        const uint32_t aLoB = aHiB + 10240;
        const uint32_t bHiB = aHiB + 20480;
        const uint32_t bLoB = aHiB + 25088;

        #pragma unroll
        for (int ks = 0; ks < 2; ks++) {
            const int k0 = ks * 16;
            uint32_t ah[2][4], al[2][4];
            #pragma unroll
            for (int mi = 0; mi < 2; mi++) {
                int row = wm * 32 + mi * 16 + (lane & 15);
                uint32_t off = (uint32_t)(row * 40 + k0 + (lane >> 4) * 8) * 2;
                ldsm_x4(ah[mi], aHiB + off);
                ldsm_x4(al[mi], aLoB + off);
            }
            #pragma unroll
            for (int nc = 0; nc < 2; nc++) {
                int krow = k0 + (lane & 15);
                int ncol = wn * 32 + nc * 16 + (lane >> 4) * 8;
                uint32_t off = (uint32_t)(krow * 72 + ncol) * 2;
                uint32_t bh[4], bl[4];
                ldsm_x4_t(bh, bHiB + off);
                ldsm_x4_t(bl, bLoB + off);
                #pragma unroll
                for (int mi = 0; mi < 2; mi++) {
                    mma_bf16(acc[mi][nc*2+0], ah[mi], bh);
                    mma_bf16(acc[mi][nc*2+0], al[mi], bh);
                    mma_bf16(acc[mi][nc*2+0], ah[mi], bl);
                    mma_bf16(acc[mi][nc*2+1], ah[mi], bh + 2);
                    mma_bf16(acc[mi][nc*2+1], al[mi], bh + 2);
                    mma_bf16(acc[mi][nc*2+1], ah[mi], bl + 2);
                }
            }
        }
        __syncthreads();
    }

    // Epilogue: bias + tanh + store
    #pragma unroll
    for (int mi = 0; mi < 2; mi++) {
        #pragma unroll
        for (int ni = 0; ni < 4; ni++) {
            int m_g = m0 + wm * 32 + mi * 16 + (lane >> 2);
            int n_g = n0 + wn * 32 + ni * 8 + (lane & 3) * 2;
            float2 bv = *(const float2*)&bias[n_g];
            float2 o0, o1;
            o0.x = tanhf(acc[mi][ni][0] + bv.x);
            o0.y = tanhf(acc[mi][ni][1] + bv.y);
            o1.x = tanhf(acc[mi][ni][2] + bv.x);
            o1.y = tanhf(acc[mi][ni][3] + bv.y);
            *(float2*)&dst[(size_t)m_g * 512 + n_g] = o0;
            *(float2*)&dst[(size_t)(m_g + 8) * 512 + n_g] = o1;
        }
    }
}

// ---------------------------------------------------------------------------
// Barrier-free dual attention, float4 per thread.
// Block = (d-tile 32, t-half 16, b), 128 threads: thread = (t, d-quad),
// owns full s range -> thread-local softmax (tanh-bounded logits, no max).
// Grid 256 blocks, 96KB smem -> 2 blocks/SM.
// ---------------------------------------------------------------------------
__global__ void __launch_bounds__(128)
attn_kernel(const float* __restrict__ H, const float* __restrict__ F,
            const float* __restrict__ Amat, const float* __restrict__ Cmat,
            const float* __restrict__ enc, const float* __restrict__ outp,
            float* __restrict__ concat, float* __restrict__ attn)
{
    extern __shared__ float sm[];
    float* Hs = sm;            // [256][32]
    float* Fs = sm + 8192;     // [256][32]
    float* Es = sm + 16384;    // [256][32]

    const int tid = threadIdx.x;
    const int dq  = (tid & 7) * 4;
    const int t   = blockIdx.y * 16 + (tid >> 3);
    const int d0  = blockIdx.x * 32;
    const int b   = blockIdx.z;

    for (int idx = tid; idx < 2048; idx += 128) {
        int s  = idx >> 3;
        int dl = (idx & 7) << 2;
        size_t g = ((size_t)(b * Ss + s)) * Dd + d0 + dl;
        *(float4*)&Hs[s * 32 + dl] = *(const float4*)&H[g];
        *(float4*)&Fs[s * 32 + dl] = *(const float4*)&F[g];
        *(float4*)&Es[s * 32 + dl] = *(const float4*)&enc[g];
    }
    __syncthreads();

    const int m = b * Tt + t;
    const float L2E = 1.4426950408889634f;
    float4 a4 = *(const float4*)&Amat[(size_t)m * Dd + d0 + dq];
    float4 c4 = *(const float4*)&Cmat[(size_t)m * Dd + d0 + dq];
    a4.x *= L2E; a4.y *= L2E; a4.z *= L2E; a4.w *= L2E;
    c4.x *= L2E; c4.y *= L2E; c4.z *= L2E; c4.w *= L2E;

    // Pass 1: softmax denominators (thread-local)
    float sx = 0.f, sy = 0.f, sz = 0.f, sw = 0.f;
    #pragma unroll 4
    for (int s = 0; s < Ss; s++) {
        float4 h = *(const float4*)&Hs[s * 32 + dq];
        float4 f = *(const float4*)&Fs[s * 32 + dq];
        sx += exp2f(fmaf(a4.x, h.x, c4.x * f.x));
        sy += exp2f(fmaf(a4.y, h.y, c4.y * f.y));
        sz += exp2f(fmaf(a4.z, h.z, c4.z * f.z));
        sw += exp2f(fmaf(a4.w, h.w, c4.w * f.w));
    }
    const float ix = 1.f / sx, iy = 1.f / sy, iz = 1.f / sz, iw = 1.f / sw;

    // Pass 2: write gamma (STG.128) + accumulate context
    float cx = 0.f, cy = 0.f, cz = 0.f, cw = 0.f;
    float* ab = attn + (size_t)m * Ss * Dd + d0 + dq;
    #pragma unroll 2
    for (int s = 0; s < Ss; s++) {
        float4 h = *(const float4*)&Hs[s * 32 + dq];
        float4 f = *(const float4*)&Fs[s * 32 + dq];
        float4 e = *(const float4*)&Es[s * 32 + dq];
        float4 gv;
        gv.x = exp2f(fmaf(a4.x, h.x, c4.x * f.x)) * ix;
        gv.y = exp2f(fmaf(a4.y, h.y, c4.y * f.y)) * iy;
        gv.z = exp2f(fmaf(a4.z, h.z, c4.z * f.z)) * iz;
        gv.w = exp2f(fmaf(a4.w, h.w, c4.w * f.w)) * iw;
        *(float4*)&ab[(size_t)s * Dd] = gv;
        cx = fmaf(gv.x, e.x, cx);
        cy = fmaf(gv.y, e.y, cy);
        cz = fmaf(gv.z, e.z, cz);
        cw = fmaf(gv.w, e.w, cw);
    }

    float4 ct; ct.x = cx; ct.y = cy; ct.z = cz; ct.w = cw;
    *(float4*)&concat[(size_t)m * (2 * Dd) + Dd + d0 + dq] = ct;
    *(float4*)&concat[(size_t)m * (2 * Dd) + d0 + dq] =
        *(const float4*)&outp[(size_t)m * Dd + d0 + dq];
}

// ---------------------------------------------------------------------------
extern "C" void kernel_launch(void* const* d_in, const int* in_sizes, int n_in,
                              void* d_out, int out_size)
{
    const float* output = (const float*)d_in[0];   // [8,32,512]
    const float* enc    = (const float*)d_in[1];   // [256,8,512] flat [2048,512]
    const float* z      = (const float*)d_in[2];   // [8,256,128] flat [2048,128]
    const float* W1 = (const float*)d_in[3];
    const float* b1 = (const float*)d_in[4];
    const float* W2 = (const float*)d_in[5];
    const float* b2 = (const float*)d_in[6];
    const float* W3 = (const float*)d_in[7];
    const float* b3 = (const float*)d_in[8];
    const float* W4 = (const float*)d_in[9];
    const float* b4 = (const float*)d_in[10];

    float* concat = (float*)d_out;                       // [8,32,1024]
    float* attn   = concat + (size_t)Bb * Tt * 2 * Dd;   // [8,32,256,512]

    float *pH, *pF, *pA, *pC;
    cudaGetSymbolAddress((void**)&pH, g_H);
    cudaGetSymbolAddress((void**)&pF, g_F);
    cudaGetSymbolAddress((void**)&pA, g_A);
    cudaGetSymbolAddress((void**)&pC, g_C);

    convert_all<<<560, 1024>>>(enc, z, output, W1, W2, W3, W4);

    cudaFuncSetAttribute(megagemm_mma, cudaFuncAttributeMaxDynamicSharedMemorySize, GEMM_SMEM);
    megagemm_mma<<<288, 256, GEMM_SMEM>>>(b1, b2, b3, b4, pH, pF, pA, pC);

    const int smem_attn = 3 * 8192 * (int)sizeof(float);  // 98304
    cudaFuncSetAttribute(attn_kernel, cudaFuncAttributeMaxDynamicSharedMemorySize, smem_attn);
    attn_kernel<<<dim3(16, 2, Bb), 128, smem_attn>>>(pH, pF, pA, pC, enc, output, concat, attn);
}